// round 15
// baseline (speedup 1.0000x reference)
#include <cuda_runtime.h>
#include <cuda_bf16.h>
#include <cuda_fp16.h>
#include <cstdint>

#define CN0 200000
#define CN1 50000
#define CN2 12500
#define CE0 3200000
#define CE1 800000
#define CE2 200000
#define NT (CN0 + CN1 + CN2)
#define ET (CE0 + CE1 + CE2)

// ---------------- scratch ----------------
__device__ __align__(16) float g_A0[CN0 * 128];   // half-aliased agg input
__device__ __align__(16) float g_B0[CN0 * 128];
__device__ __align__(16) float g_E0[CN0 * 128];
__device__ __align__(16) float g_T0[CN0 * 4];
__device__ __align__(16) float g_XS[CN0 * 4];
__device__ __align__(16) float g_X1[CN1 * 128];
__device__ __align__(16) float g_A1[CN1 * 128];   // half-aliased agg input
__device__ __align__(16) float g_B1[CN1 * 128];
__device__ __align__(16) float g_E1[CN1 * 128];
__device__ __align__(16) float g_X2[CN2 * 128];
__device__ __align__(16) float g_A2[CN2 * 128];   // half-aliased agg input
__device__ __align__(16) float g_Y2[CN2 * 128];   // fp32 y_top2 (addsrc)
__device__ __align__(16) float g_BT[CN2 * 128];

__device__ int   g_degA[NT];
__device__ int   g_curA[NT];
__device__ float g_invA[NT];
__device__ int   g_rpA[NT + 3];
__device__ int   g_bsumA[66];
__device__ int   g_col0[CE0];
__device__ int   g_col1[CE1];
__device__ int   g_col2[CE2];

#define WCH4 1152
__device__ __align__(16) uint4 g_W[44 * WCH4];

#define SCAN_CHUNK 4096

struct EArgs {
    const int* s0; const int* d0;
    const int* s1; const int* d1;
    const int* s2; const int* d2;
};
struct WArgs { const float* w[9]; };

// ---------------- bf16 split helpers ----------------
__device__ __forceinline__ void bf16_split2(float a, float b, uint32_t& hi, uint32_t& lo) {
    __nv_bfloat16 ah = __float2bfloat16(a);
    __nv_bfloat16 bh = __float2bfloat16(b);
    __nv_bfloat16 al = __float2bfloat16(a - __bfloat162float(ah));
    __nv_bfloat16 bl = __float2bfloat16(b - __bfloat162float(bh));
    hi = ((uint32_t)__bfloat16_as_ushort(bh) << 16) | (uint32_t)__bfloat16_as_ushort(ah);
    lo = ((uint32_t)__bfloat16_as_ushort(bl) << 16) | (uint32_t)__bfloat16_as_ushort(al);
}

// ---------------- merged weight pre-split + degree count (one launch) ----------------
__global__ void k_wsplit_deg(WArgs a, uint4* __restrict__ img,
                             EArgs ea, int* __restrict__ degA) {
    if (blockIdx.x < 44) {
        const int starts[10] = {0, 4, 8, 12, 16, 20, 24, 28, 36, 44};
        int b = blockIdx.x, tid = threadIdx.x;
        int wi = 0;
#pragma unroll
        for (int q = 0; q < 9; q++) if (b >= starts[q + 1]) wi = q + 1;
        int lc = b - starts[wi];
        const float* W = a.w[wi];
        uint4* out = img + b * WCH4;
#pragma unroll
        for (int it = 0; it < 4; it++) {
            int p = tid + it * 256;
            int cn = p >> 3, r = p & 7, ks = r >> 2, t = r & 3;
            int k0 = lc * 32 + ks * 16 + 2 * t;
            float w00 = W[(size_t)k0 * 128 + cn];
            float w01 = W[(size_t)(k0 + 1) * 128 + cn];
            float w10 = W[(size_t)(k0 + 8) * 128 + cn];
            float w11 = W[(size_t)(k0 + 9) * 128 + cn];
            uint32_t h0, l0, h1, l1;
            bf16_split2(w00, w01, h0, l0);
            bf16_split2(w10, w11, h1, l1);
            out[cn * 9 + ks * 4 + t] = make_uint4(h0, h1, l0, l1);
        }
        for (int p = tid; p < 128; p += 256) out[p * 9 + 8] = make_uint4(0, 0, 0, 0);
    } else {
        int i = (blockIdx.x - 44) * blockDim.x + threadIdx.x;
        if (i >= ET) return;
        int d, off;
        if (i < CE0)            { d = ea.d0[i]; off = 0; }
        else if (i < CE0 + CE1) { d = ea.d1[i - CE0]; off = CN0; }
        else                    { d = ea.d2[i - CE0 - CE1]; off = CN0 + CN1; }
        atomicAdd(&degA[off + d], 1);
    }
}

__global__ void k_scan_part_all(const int* __restrict__ degA, int* __restrict__ bsum) {
    __shared__ int wsum[32];
    int b = blockIdx.x;
    int lb, n, doff;
    if (b < 49)      { lb = b;      n = CN0; doff = 0; }
    else if (b < 62) { lb = b - 49; n = CN1; doff = CN0; }
    else             { lb = b - 62; n = CN2; doff = CN0 + CN1; }
    const int* deg = degA + doff;
    int base = lb * SCAN_CHUNK + threadIdx.x * 4;
    int s = 0;
#pragma unroll
    for (int j = 0; j < 4; j++) if (base + j < n) s += deg[base + j];
    int lane = threadIdx.x & 31, wid = threadIdx.x >> 5;
#pragma unroll
    for (int off = 16; off > 0; off >>= 1) s += __shfl_down_sync(0xFFFFFFFFu, s, off);
    if (lane == 0) wsum[wid] = s;
    __syncthreads();
    if (threadIdx.x < 32) {
        int v = wsum[threadIdx.x];
#pragma unroll
        for (int off = 16; off > 0; off >>= 1) v += __shfl_down_sync(0xFFFFFFFFu, v, off);
        if (threadIdx.x == 0) bsum[b] = v;
    }
}

__global__ void k_scan_top_all(int* __restrict__ bsum, int* __restrict__ rpA) {
    int lv = blockIdx.x;
    int bstart = (lv == 0) ? 0 : (lv == 1) ? 49 : 62;
    int nb     = (lv == 0) ? 49 : (lv == 1) ? 13 : 4;
    int n      = (lv == 0) ? CN0 : (lv == 1) ? CN1 : CN2;
    int rpo    = (lv == 0) ? 0 : (lv == 1) ? CN0 + 1 : CN0 + CN1 + 2;
    int t = threadIdx.x;
    __shared__ int sh[64];
    sh[t] = (t < nb) ? bsum[bstart + t] : 0;
    __syncthreads();
    for (int off = 1; off < 64; off <<= 1) {
        int v = (t >= off) ? sh[t - off] : 0;
        __syncthreads();
        sh[t] += v;
        __syncthreads();
    }
    if (t < nb) bsum[bstart + t] = (t == 0) ? 0 : sh[t - 1];
    if (t == 63) rpA[rpo + n] = sh[63];
}

__global__ void k_scan_down_all(const int* __restrict__ degA, const int* __restrict__ bsum,
                                int* __restrict__ rpA, int* __restrict__ curA,
                                float* __restrict__ invA,
                                const float4* __restrict__ x, float4* __restrict__ xs) {
    __shared__ int wsum[32];
    int b = blockIdx.x;
    int lv, lb, n, doff, rpo;
    if (b < 49)      { lv = 0; lb = b;      n = CN0; doff = 0;        rpo = 0; }
    else if (b < 62) { lv = 1; lb = b - 49; n = CN1; doff = CN0;      rpo = CN0 + 1; }
    else             { lv = 2; lb = b - 62; n = CN2; doff = CN0 + CN1; rpo = CN0 + CN1 + 2; }
    const int* deg = degA + doff;
    int* rp = rpA + rpo;
    int* cur = curA + doff;
    float* inv = invA + doff;

    int base = lb * SCAN_CHUNK + threadIdx.x * 4;
    int d[4];
#pragma unroll
    for (int j = 0; j < 4; j++) d[j] = (base + j < n) ? deg[base + j] : 0;
    int tot = d[0] + d[1] + d[2] + d[3];
    int lane = threadIdx.x & 31, wid = threadIdx.x >> 5;
    int sc = tot;
#pragma unroll
    for (int off = 1; off < 32; off <<= 1) {
        int v = __shfl_up_sync(0xFFFFFFFFu, sc, off);
        if (lane >= off) sc += v;
    }
    if (lane == 31) wsum[wid] = sc;
    __syncthreads();
    if (threadIdx.x < 32) {
        int v = wsum[threadIdx.x];
#pragma unroll
        for (int off = 1; off < 32; off <<= 1) {
            int u = __shfl_up_sync(0xFFFFFFFFu, v, off);
            if (threadIdx.x >= off) v += u;
        }
        wsum[threadIdx.x] = v;
    }
    __syncthreads();
    int run = bsum[b] + (sc - tot) + (wid > 0 ? wsum[wid - 1] : 0);
#pragma unroll
    for (int j = 0; j < 4; j++) {
        int row = base + j;
        if (row < n) {
            rp[row] = run;
            cur[row] = run;
            float iv = rsqrtf((float)(d[j] + 1));
            inv[row] = iv;
            if (lv == 0) {
                float4 v = x[row];
                xs[row] = make_float4(v.x * iv, v.y * iv, v.z * iv, v.w * iv);
            }
            run += d[j];
        }
    }
}

__global__ void k_fill_all(EArgs ea, int* __restrict__ curA,
                           int* __restrict__ col0, int* __restrict__ col1,
                           int* __restrict__ col2) {
    int i = blockIdx.x * blockDim.x + threadIdx.x;
    if (i >= ET) return;
    int s, d, off;
    int* col;
    if (i < CE0)            { s = ea.s0[i]; d = ea.d0[i]; off = 0; col = col0; }
    else if (i < CE0 + CE1) { int e = i - CE0; s = ea.s1[e]; d = ea.d1[e]; off = CN0; col = col1; }
    else                    { int e = i - CE0 - CE1; s = ea.s2[e]; d = ea.d2[e]; off = CN0 + CN1; col = col2; }
    int p = atomicAdd(&curA[off + d], 1);
    col[p] = s;
}

// ---------------- aggregation over 4-wide pre-scaled features ----------------
__global__ void k_agg4(const float4* __restrict__ xs, float4* __restrict__ out,
                       const int* __restrict__ rp, const int* __restrict__ col,
                       const float* __restrict__ inv, int n) {
    int r = blockIdx.x * blockDim.x + threadIdx.x;
    if (r >= n) return;
    float4 acc = xs[r];
    int e = rp[r], end = rp[r + 1];
    for (; e + 4 <= end; e += 4) {
        int s0 = col[e], s1 = col[e + 1], s2 = col[e + 2], s3 = col[e + 3];
        float4 v0 = xs[s0], v1 = xs[s1], v2 = xs[s2], v3 = xs[s3];
        acc.x += v0.x + v1.x + v2.x + v3.x;
        acc.y += v0.y + v1.y + v2.y + v3.y;
        acc.z += v0.z + v1.z + v2.z + v3.z;
        acc.w += v0.w + v1.w + v2.w + v3.w;
    }
    for (; e < end; e++) {
        float4 v0 = xs[col[e]];
        acc.x += v0.x; acc.y += v0.y; acc.z += v0.z; acc.w += v0.w;
    }
    float invd = inv[r];
    out[r] = make_float4(acc.x * invd, acc.y * invd, acc.z * invd, acc.w * invd);
}

// ---------------- half-row load helper ----------------
__device__ __forceinline__ float4 ld_half4(const __half2* hp, int row, int lane) {
    uint2 u = *(const uint2*)(hp + (size_t)row * 64 + lane * 2);
    __half2 p0 = *(__half2*)&u.x;
    __half2 p1 = *(__half2*)&u.y;
    float2 f0 = __half22float2(p0);
    float2 f1 = __half22float2(p1);
    return make_float4(f0.x, f0.y, f1.x, f1.y);
}

// ---------------- aggregation 128-wide + bias + relu ----------------
template <bool POOL, bool HALF_IN>
__global__ void k_agg128(const void* __restrict__ hv, float4* __restrict__ out,
                         const int* __restrict__ rp, const int* __restrict__ col,
                         const float* __restrict__ inv, const float* __restrict__ bias,
                         int* __restrict__ pool, const int* __restrict__ clusters, int n) {
    int row = blockIdx.x * blockDim.y + threadIdx.y;
    if (row >= n) return;
    int lane = threadIdx.x;
    const float4* hf = (const float4*)hv;
    const __half2* hh = (const __half2*)hv;
    float4 acc = HALF_IN ? ld_half4(hh, row, lane) : hf[row * 32 + lane];
    int e = rp[row], end = rp[row + 1];
    for (; e + 4 <= end; e += 4) {
        int s0 = col[e], s1 = col[e + 1], s2 = col[e + 2], s3 = col[e + 3];
        float4 v0, v1, v2, v3;
        if (HALF_IN) {
            v0 = ld_half4(hh, s0, lane); v1 = ld_half4(hh, s1, lane);
            v2 = ld_half4(hh, s2, lane); v3 = ld_half4(hh, s3, lane);
        } else {
            v0 = hf[s0 * 32 + lane]; v1 = hf[s1 * 32 + lane];
            v2 = hf[s2 * 32 + lane]; v3 = hf[s3 * 32 + lane];
        }
        acc.x += v0.x + v1.x + v2.x + v3.x;
        acc.y += v0.y + v1.y + v2.y + v3.y;
        acc.z += v0.z + v1.z + v2.z + v3.z;
        acc.w += v0.w + v1.w + v2.w + v3.w;
    }
    for (; e < end; e++) {
        float4 v0 = HALF_IN ? ld_half4(hh, col[e], lane) : hf[col[e] * 32 + lane];
        acc.x += v0.x; acc.y += v0.y; acc.z += v0.z; acc.w += v0.w;
    }
    float invd = inv[row];
    int cb = lane * 4;
    acc.x = fmaxf(acc.x * invd + bias[cb + 0], 0.f);
    acc.y = fmaxf(acc.y * invd + bias[cb + 1], 0.f);
    acc.z = fmaxf(acc.z * invd + bias[cb + 2], 0.f);
    acc.w = fmaxf(acc.w * invd + bias[cb + 3], 0.f);
    out[row * 32 + lane] = acc;
    if (POOL) {
        int c = clusters[row];
        int base = c * 128 + cb;
        atomicMax(&pool[base + 0], __float_as_int(acc.x));
        atomicMax(&pool[base + 1], __float_as_int(acc.y));
        atomicMax(&pool[base + 2], __float_as_int(acc.z));
        atomicMax(&pool[base + 3], __float_as_int(acc.w));
    }
}

// ---------------- final aggregation fused with output head (half input) ----------------
__global__ void k_agg128_head(const __half2* __restrict__ hh, float* __restrict__ out,
                              const int* __restrict__ rp, const int* __restrict__ col,
                              const float* __restrict__ inv, const float* __restrict__ bias,
                              const float* __restrict__ wout, const float* __restrict__ bout,
                              int n) {
    int row = blockIdx.x * blockDim.y + threadIdx.y;
    if (row >= n) return;
    int lane = threadIdx.x;
    float4 acc = ld_half4(hh, row, lane);
    int e = rp[row], end = rp[row + 1];
    for (; e + 4 <= end; e += 4) {
        int s0 = col[e], s1 = col[e + 1], s2 = col[e + 2], s3 = col[e + 3];
        float4 v0 = ld_half4(hh, s0, lane);
        float4 v1 = ld_half4(hh, s1, lane);
        float4 v2 = ld_half4(hh, s2, lane);
        float4 v3 = ld_half4(hh, s3, lane);
        acc.x += v0.x + v1.x + v2.x + v3.x;
        acc.y += v0.y + v1.y + v2.y + v3.y;
        acc.z += v0.z + v1.z + v2.z + v3.z;
        acc.w += v0.w + v1.w + v2.w + v3.w;
    }
    for (; e < end; e++) {
        float4 v0 = ld_half4(hh, col[e], lane);
        acc.x += v0.x; acc.y += v0.y; acc.z += v0.z; acc.w += v0.w;
    }
    float invd = inv[row];
    int cb = lane * 4;
    float a0 = fmaxf(acc.x * invd + bias[cb + 0], 0.f);
    float a1 = fmaxf(acc.y * invd + bias[cb + 1], 0.f);
    float a2 = fmaxf(acc.z * invd + bias[cb + 2], 0.f);
    float a3 = fmaxf(acc.w * invd + bias[cb + 3], 0.f);
    float4 wv = *(const float4*)&wout[cb];
    float s = a0 * wv.x + a1 * wv.y + a2 * wv.z + a3 * wv.w;
#pragma unroll
    for (int off = 16; off > 0; off >>= 1) s += __shfl_down_sync(0xFFFFFFFFu, s, off);
    if (lane == 0) out[row] = s + bout[0];
}

// =====================================================================
//  bf16 mma.sync GEMM (fp32 A, cp.async staged; HALF_OUT toggles fp16 store)
// =====================================================================
#define SMB_A 16384
#define SMB_W (WCH4 * 16)
#define SMB_RAW 16384
#define SMB_RAW_OFF (SMB_A + 2 * SMB_W)
#define SMB_TOT (SMB_RAW_OFF + 2 * SMB_RAW)
#define SMB_TOT_E0 (SMB_RAW_OFF + 2560)

__device__ __forceinline__ uint32_t smem_u32(const void* p) {
    uint32_t a;
    asm("{ .reg .u64 t; cvta.to.shared.u64 t, %1; cvt.u32.u64 %0, t; }" : "=r"(a) : "l"(p));
    return a;
}

__device__ __forceinline__ void cpa16(uint32_t saddr, const void* g) {
    asm volatile("cp.async.cg.shared.global [%0], [%1], 16;" :: "r"(saddr), "l"(g) : "memory");
}

__device__ __forceinline__ void cpa16z(uint32_t saddr, const void* g, int sz) {
    asm volatile("cp.async.cg.shared.global [%0], [%1], 16, %2;"
                 :: "r"(saddr), "l"(g), "r"(sz) : "memory");
}

__device__ __forceinline__ void copy_w_chunk(uint32_t sdst, const uint4* gsrc, int tid) {
#pragma unroll
    for (int it = 0; it < 5; it++) {
        int g = tid + it * 256;
        if (g < WCH4) cpa16(sdst + g * 16, gsrc + g);
    }
}

__device__ __forceinline__ void copy_a_chunk(uint32_t sdst, const float* A, int r0,
                                             int kc, int n, int tid) {
#pragma unroll
    for (int it = 0; it < 4; it++) {
        int g = tid + it * 256;
        int row = g >> 3, seg = g & 7;
        const float* src = A + (size_t)(r0 + row) * 128 + kc + seg * 4;
        int sz = (r0 + row < n) ? 16 : 0;
        cpa16z(sdst + g * 16, src, sz);
    }
}

__device__ __forceinline__ void mma_bf16(float* c, uint4 a, uint32_t b0, uint32_t b1) {
    asm volatile(
        "mma.sync.aligned.m16n8k16.row.col.f32.bf16.bf16.f32 "
        "{%0,%1,%2,%3}, {%4,%5,%6,%7}, {%8,%9}, {%0,%1,%2,%3};"
        : "+f"(c[0]), "+f"(c[1]), "+f"(c[2]), "+f"(c[3])
        : "r"(a.x), "r"(a.y), "r"(a.z), "r"(a.w), "r"(b0), "r"(b1));
}

template <bool HALF_OUT>
__device__ __forceinline__ void st_out(float* Cm, int row, int cn, float2 o) {
    if (HALF_OUT) {
        __half2 h = __floats2half2_rn(o.x, o.y);
        ((__half2*)Cm)[(size_t)row * 64 + (cn >> 1)] = h;
    } else {
        *(float2*)&Cm[(size_t)row * 128 + cn] = o;
    }
}

template <bool ADD_GATHER, bool HALF_OUT>
__global__ void __launch_bounds__(256, 2) k_gemm_mma(
    const float* __restrict__ A, const uint4* __restrict__ gW,
    float* __restrict__ Cm, int n,
    const float* __restrict__ scale,
    const float* __restrict__ addsrc, const int* __restrict__ gidx) {
    extern __shared__ char smem[];
    uint32_t* AHu = (uint32_t*)smem;
    uint32_t* ALu = AHu + 2048;
    const uint4* AH4 = (const uint4*)smem;
    const uint4* AL4 = AH4 + 512;
    uint32_t sb = smem_u32(smem);

    int tid = threadIdx.x;
    int warp = tid >> 5, lane = tid & 31;
    int g = lane >> 2, t = lane & 3;
    int mrow = (warp & 3) * 32;
    int ncol = (warp >> 2) * 64;
    int r0 = blockIdx.x * 128;

    float c[2][8][4];
#pragma unroll
    for (int i = 0; i < 2; i++)
#pragma unroll
        for (int j = 0; j < 8; j++)
#pragma unroll
            for (int q = 0; q < 4; q++) c[i][j][q] = 0.f;

    copy_w_chunk(sb + SMB_A, gW, tid);
    copy_a_chunk(sb + SMB_RAW_OFF, A, r0, 0, n, tid);
    asm volatile("cp.async.commit_group;" ::: "memory");

#pragma unroll
    for (int cc = 0; cc < 4; cc++) {
        if (cc < 3) {
            int nb = (cc + 1) & 1;
            copy_w_chunk(sb + SMB_A + nb * SMB_W, gW + (cc + 1) * WCH4, tid);
            copy_a_chunk(sb + SMB_RAW_OFF + nb * SMB_RAW, A, r0, (cc + 1) * 32, n, tid);
            asm volatile("cp.async.commit_group;" ::: "memory");
            asm volatile("cp.async.wait_group 1;" ::: "memory");
        } else {
            asm volatile("cp.async.wait_group 0;" ::: "memory");
        }
        __syncthreads();

        const float* raw = (const float*)(smem + SMB_RAW_OFF + (cc & 1) * SMB_RAW);
#pragma unroll
        for (int it = 0; it < 8; it++) {
            int p = tid + it * 256;
            int row = p >> 4, kp = p & 15;
            float2 av = *(const float2*)&raw[row * 32 + 2 * kp];
            uint32_t hi, lo;
            bf16_split2(av.x, av.y, hi, lo);
            int s = row & 15, rg = row >> 4;
            int ks = kp >> 3, kp8 = kp & 7, tt = kp8 & 3, half = kp8 >> 2;
            int idx = (((rg * 2 + ks) * 32) + (s & 7) * 4 + tt) * 4 + half * 2 + (s >> 3);
            AHu[idx] = hi;
            ALu[idx] = lo;
        }
        __syncthreads();

        const uint4* B4 = (const uint4*)(smem + SMB_A + (cc & 1) * SMB_W);

#pragma unroll
        for (int ks = 0; ks < 2; ks++) {
            uint4 ah[2], al[2];
#pragma unroll
            for (int i = 0; i < 2; i++) {
                int grp = (((warp & 3) * 2 + i) * 2 + ks) * 32 + lane;
                ah[i] = AH4[grp];
                al[i] = AL4[grp];
            }
#pragma unroll
            for (int j = 0; j < 8; j++) {
                int cn = ncol + j * 8 + g;
                uint4 b4 = B4[cn * 9 + ks * 4 + t];
#pragma unroll
                for (int i = 0; i < 2; i++) {
                    mma_bf16(c[i][j], ah[i], b4.x, b4.y);
                    mma_bf16(c[i][j], al[i], b4.x, b4.y);
                    mma_bf16(c[i][j], ah[i], b4.z, b4.w);
                }
            }
        }
        __syncthreads();
    }

#pragma unroll
    for (int i = 0; i < 2; i++) {
        int rowA = r0 + mrow + i * 16 + g;
        int rowB = rowA + 8;
        int gA = 0, gB = 0;
        float sA = 1.f, sB = 1.f;
        if (ADD_GATHER) {
            if (rowA < n) gA = gidx[rowA];
            if (rowB < n) gB = gidx[rowB];
        }
        if (scale) {
            if (rowA < n) sA = scale[rowA];
            if (rowB < n) sB = scale[rowB];
        }
#pragma unroll
        for (int j = 0; j < 8; j++) {
            int cn = ncol + j * 8 + 2 * t;
            if (rowA < n) {
                float2 o = make_float2(c[i][j][0], c[i][j][1]);
                if (ADD_GATHER) {
                    o.x += addsrc[(size_t)gA * 128 + cn];
                    o.y += addsrc[(size_t)gA * 128 + cn + 1];
                }
                o.x *= sA; o.y *= sA;
                st_out<HALF_OUT>(Cm, rowA, cn, o);
            }
            if (rowB < n) {
                float2 o = make_float2(c[i][j][2], c[i][j][3]);
                if (ADD_GATHER) {
                    o.x += addsrc[(size_t)gB * 128 + cn];
                    o.y += addsrc[(size_t)gB * 128 + cn + 1];
                }
                o.x *= sB; o.y *= sB;
                st_out<HALF_OUT>(Cm, rowB, cn, o);
            }
        }
    }
}

// fused first-layer variant (half output)
__global__ void __launch_bounds__(256, 2) k_gemm_e0(
    const float4* __restrict__ T0, const float* __restrict__ W0,
    const float* __restrict__ b0, const uint4* __restrict__ gW,
    float* __restrict__ Cm, int n, const float* __restrict__ scale) {
    extern __shared__ char smem[];
    uint32_t* AHu = (uint32_t*)smem;
    uint32_t* ALu = AHu + 2048;
    const uint4* AH4 = (const uint4*)smem;
    const uint4* AL4 = AH4 + 512;
    float* Ws = (float*)(smem + SMB_RAW_OFF);
    float* Bs = Ws + 512;
    uint32_t sb = smem_u32(smem);

    int tid = threadIdx.x;
    int warp = tid >> 5, lane = tid & 31;
    int g = lane >> 2, t = lane & 3;
    int mrow = (warp & 3) * 32;
    int ncol = (warp >> 2) * 64;
    int r0 = blockIdx.x * 128;

    for (int i = tid; i < 512; i += 256) Ws[i] = W0[i];
    if (tid < 128) Bs[tid] = b0[tid];

    float c[2][8][4];
#pragma unroll
    for (int i = 0; i < 2; i++)
#pragma unroll
        for (int j = 0; j < 8; j++)
#pragma unroll
            for (int q = 0; q < 4; q++) c[i][j][q] = 0.f;

    copy_w_chunk(sb + SMB_A, gW, tid);
    asm volatile("cp.async.commit_group;" ::: "memory");
    __syncthreads();

#pragma unroll
    for (int cc = 0; cc < 4; cc++) {
        int kc = cc * 32;
#pragma unroll
        for (int it = 0; it < 8; it++) {
            int p = tid + it * 256;
            int row = p >> 4, kp = p & 15;
            float v0 = 0.f, v1 = 0.f;
            if (r0 + row < n) {
                float4 t4 = T0[r0 + row];
                int cx = kc + 2 * kp;
                v0 = fmaxf(Bs[cx] + t4.x * Ws[cx] + t4.y * Ws[128 + cx]
                           + t4.z * Ws[256 + cx] + t4.w * Ws[384 + cx], 0.f);
                v1 = fmaxf(Bs[cx + 1] + t4.x * Ws[cx + 1] + t4.y * Ws[128 + cx + 1]
                           + t4.z * Ws[256 + cx + 1] + t4.w * Ws[384 + cx + 1], 0.f);
            }
            uint32_t hi, lo;
            bf16_split2(v0, v1, hi, lo);
            int s = row & 15, rg = row >> 4;
            int ks = kp >> 3, kp8 = kp & 7, tt = kp8 & 3, half = kp8 >> 2;
            int idx = (((rg * 2 + ks) * 32) + (s & 7) * 4 + tt) * 4 + half * 2 + (s >> 3);
            AHu[idx] = hi;
            ALu[idx] = lo;
        }
        if (cc < 3) {
            copy_w_chunk(sb + SMB_A + ((cc + 1) & 1) * SMB_W, gW + (cc + 1) * WCH4, tid);
            asm volatile("cp.async.commit_group;" ::: "memory");
            asm volatile("cp.async.wait_group 1;" ::: "memory");
        } else {
            asm volatile("cp.async.wait_group 0;" ::: "memory");
        }
        __syncthreads();

        const uint4* B4 = (const uint4*)(smem + SMB_A + (cc & 1) * SMB_W);

#pragma unroll
        for (int ks = 0; ks < 2; ks++) {
            uint4 ah[2], al[2];
#pragma unroll
            for (int i = 0; i < 2; i++) {
                int grp = (((warp & 3) * 2 + i) * 2 + ks) * 32 + lane;
                ah[i] = AH4[grp];
                al[i] = AL4[grp];
            }
#pragma unroll
            for (int j = 0; j < 8; j++) {
                int cn = ncol + j * 8 + g;
                uint4 b4 = B4[cn * 9 + ks * 4 + t];
#pragma unroll
                for (int i = 0; i < 2; i++) {
                    mma_bf16(c[i][j], ah[i], b4.x, b4.y);
                    mma_bf16(c[i][j], al[i], b4.x, b4.y);
                    mma_bf16(c[i][j], ah[i], b4.z, b4.w);
                }
            }
        }
        __syncthreads();
    }

#pragma unroll
    for (int i = 0; i < 2; i++) {
        int rowA = r0 + mrow + i * 16 + g;
        int rowB = rowA + 8;
        float sA = (rowA < n) ? scale[rowA] : 1.f;
        float sB = (rowB < n) ? scale[rowB] : 1.f;
#pragma unroll
        for (int j = 0; j < 8; j++) {
            int cn = ncol + j * 8 + 2 * t;
            if (rowA < n)
                st_out<true>(Cm, rowA, cn, make_float2(c[i][j][0] * sA, c[i][j][1] * sA));
            if (rowB < n)
                st_out<true>(Cm, rowB, cn, make_float2(c[i][j][2] * sB, c[i][j][3] * sB));
        }
    }
}

// ---------------- host ----------------
static inline void* symaddr(const void* sym) {
    void* p = nullptr;
    cudaGetSymbolAddress(&p, sym);
    return p;
}

extern "C" void kernel_launch(void* const* d_in, const int* in_sizes, int n_in,
                              void* d_out, int out_size) {
    const float* x     = (const float*)d_in[0];
    const int*   ei0   = (const int*)d_in[1];
    const int*   ei1   = (const int*)d_in[2];
    const int*   ei2   = (const int*)d_in[3];
    const int*   cl0   = (const int*)d_in[4];
    const int*   cl1   = (const int*)d_in[5];
    const float* w_e0a = (const float*)d_in[6];  const float* b_e0a = (const float*)d_in[7];
    const float* w_e0b = (const float*)d_in[8];  const float* b_e0b = (const float*)d_in[9];
    const float* w_e1a = (const float*)d_in[10]; const float* b_e1a = (const float*)d_in[11];
    const float* w_e1b = (const float*)d_in[12]; const float* b_e1b = (const float*)d_in[13];
    const float* w_ba  = (const float*)d_in[14]; const float* b_ba  = (const float*)d_in[15];
    const float* w_bb  = (const float*)d_in[16]; const float* b_bb  = (const float*)d_in[17];
    const float* w_d1a = (const float*)d_in[18]; const float* b_d1a = (const float*)d_in[19];
    const float* w_d1b = (const float*)d_in[20]; const float* b_d1b = (const float*)d_in[21];
    const float* w_d0a = (const float*)d_in[22]; const float* b_d0a = (const float*)d_in[23];
    const float* w_d0b = (const float*)d_in[24]; const float* b_d0b = (const float*)d_in[25];
    const float* w_out = (const float*)d_in[26]; const float* b_out = (const float*)d_in[27];
    float* out = (float*)d_out;

    float* A0 = (float*)symaddr(g_A0);
    float* B0 = (float*)symaddr(g_B0);
    float* E0f = (float*)symaddr(g_E0); float* T0 = (float*)symaddr(g_T0);
    float* XS = (float*)symaddr(g_XS);
    float* X1 = (float*)symaddr(g_X1); float* A1 = (float*)symaddr(g_A1);
    float* B1 = (float*)symaddr(g_B1); float* E1f = (float*)symaddr(g_E1);
    float* X2 = (float*)symaddr(g_X2); float* A2 = (float*)symaddr(g_A2);
    float* Y2 = (float*)symaddr(g_Y2);
    float* BT = (float*)symaddr(g_BT);

    int* degA = (int*)symaddr(g_degA);
    int* curA = (int*)symaddr(g_curA);
    float* invA = (float*)symaddr(g_invA);
    int* rpA = (int*)symaddr(g_rpA);
    int* bsA = (int*)symaddr(g_bsumA);
    int* col0 = (int*)symaddr(g_col0);
    int* col1 = (int*)symaddr(g_col1);
    int* col2 = (int*)symaddr(g_col2);
    uint4* Wimg = (uint4*)symaddr(g_W);

    int* rp0 = rpA;
    int* rp1 = rpA + CN0 + 1;
    int* rp2 = rpA + CN0 + CN1 + 2;
    float* inv0 = invA;
    float* inv1 = invA + CN0;
    float* inv2 = invA + CN0 + CN1;

    cudaFuncSetAttribute(k_gemm_mma<false, false>, cudaFuncAttributeMaxDynamicSharedMemorySize, SMB_TOT);
    cudaFuncSetAttribute(k_gemm_mma<true, true>,   cudaFuncAttributeMaxDynamicSharedMemorySize, SMB_TOT);
    cudaFuncSetAttribute(k_gemm_mma<false, true>,  cudaFuncAttributeMaxDynamicSharedMemorySize, SMB_TOT);
    cudaFuncSetAttribute(k_gemm_e0, cudaFuncAttributeMaxDynamicSharedMemorySize, SMB_TOT_E0);

    const int T = 256;
    dim3 aggB(32, 8);
    const int GB0 = (CN0 + 127) / 128, GB1 = (CN1 + 127) / 128, GB2 = (CN2 + 127) / 128;

    const int OF_E0B = 0, OF_E1A = 4, OF_E1B = 8, OF_BA = 12, OF_BB = 16,
              OF_D1B = 20, OF_D0B = 24, OF_D1A = 28, OF_D0A = 36;

    WArgs wa;
    wa.w[0] = w_e0b; wa.w[1] = w_e1a; wa.w[2] = w_e1b; wa.w[3] = w_ba; wa.w[4] = w_bb;
    wa.w[5] = w_d1b; wa.w[6] = w_d0b; wa.w[7] = w_d1a; wa.w[8] = w_d0a;

    EArgs ea;
    ea.s0 = ei0; ea.d0 = ei0 + CE0;
    ea.s1 = ei1; ea.d1 = ei1 + CE1;
    ea.s2 = ei2; ea.d2 = ei2 + CE2;

    // ---- memsets (DMA path) + merged wsplit/deg ----
    cudaMemsetAsync(degA, 0, NT * sizeof(int));
    cudaMemsetAsync(X1, 0, (size_t)CN1 * 128 * sizeof(float));
    cudaMemsetAsync(X2, 0, (size_t)CN2 * 128 * sizeof(float));
    k_wsplit_deg<<<44 + (ET + T - 1) / T, T>>>(wa, Wimg, ea, degA);
    k_scan_part_all<<<66, 1024>>>(degA, bsA);
    k_scan_top_all<<<3, 64>>>(bsA, rpA);
    k_scan_down_all<<<66, 1024>>>(degA, bsA, rpA, curA, invA, (const float4*)x, (float4*)XS);
    k_fill_all<<<(ET + T - 1) / T, T>>>(ea, curA, col0, col1, col2);

    // ---- encoder level 0 (A0 fp16) ----
    k_agg4<<<(CN0 + T - 1) / T, T>>>((const float4*)XS, (float4*)T0, rp0, col0, inv0, CN0);
    k_gemm_e0<<<GB0, 256, SMB_TOT_E0>>>((const float4*)T0, w_e0a, b_e0a,
                                        Wimg + OF_E0B * WCH4, A0, CN0, inv0);
    k_agg128<true, true><<<(CN0 + 7) / 8, aggB>>>(A0, (float4*)E0f, rp0, col0, inv0,
                                                  b_e0b, (int*)X1, cl0, CN0);

    // ---- encoder level 1 (A1 fp16) ----
    k_gemm_mma<false, true><<<GB1, 256, SMB_TOT>>>(X1, Wimg + OF_E1A * WCH4, A1, CN1, inv1, nullptr, nullptr);
    k_agg128<false, true><<<(CN1 + 7) / 8, aggB>>>(A1, (float4*)B1, rp1, col1, inv1,
                                                   b_e1a, nullptr, nullptr, CN1);
    k_gemm_mma<false, true><<<GB1, 256, SMB_TOT>>>(B1, Wimg + OF_E1B * WCH4, A1, CN1, inv1, nullptr, nullptr);
    k_agg128<true, true><<<(CN1 + 7) / 8, aggB>>>(A1, (float4*)E1f, rp1, col1, inv1,
                                                  b_e1b, (int*)X2, cl1, CN1);

    // ---- bottom level 2 (A2 fp16) ----
    k_gemm_mma<false, true><<<GB2, 256, SMB_TOT>>>(X2, Wimg + OF_BA * WCH4, A2, CN2, inv2, nullptr, nullptr);
    k_agg128<false, true><<<(CN2 + 7) / 8, aggB>>>(A2, (float4*)BT, rp2, col2, inv2,
                                                   b_ba, nullptr, nullptr, CN2);
    k_gemm_mma<false, true><<<GB2, 256, SMB_TOT>>>(BT, Wimg + OF_BB * WCH4, A2, CN2, inv2, nullptr, nullptr);
    k_agg128<false, true><<<(CN2 + 7) / 8, aggB>>>(A2, (float4*)BT, rp2, col2, inv2,
                                                   b_bb, nullptr, nullptr, CN2);

    // ---- decoder level 1 ----
    k_gemm_mma<false, false><<<GB2, 256, SMB_TOT>>>(BT, Wimg + OF_D1A * WCH4, Y2, CN2, nullptr, nullptr, nullptr);
    k_gemm_mma<true, true><<<GB1, 256, SMB_TOT>>>(E1f, Wimg + (OF_D1A + 4) * WCH4, A1, CN1, inv1, Y2, cl1);
    k_agg128<false, true><<<(CN1 + 7) / 8, aggB>>>(A1, (float4*)B1, rp1, col1, inv1,
                                                   b_d1a, nullptr, nullptr, CN1);
    k_gemm_mma<false, true><<<GB1, 256, SMB_TOT>>>(B1, Wimg + OF_D1B * WCH4, A1, CN1, inv1, nullptr, nullptr);
    k_agg128<false, true><<<(CN1 + 7) / 8, aggB>>>(A1, (float4*)X1, rp1, col1, inv1,
                                                   b_d1b, nullptr, nullptr, CN1);

    // ---- decoder level 0 ----
    k_gemm_mma<false, false><<<GB1, 256, SMB_TOT>>>(X1, Wimg + OF_D0A * WCH4, B1, CN1, nullptr, nullptr, nullptr);
    k_gemm_mma<true, true><<<GB0, 256, SMB_TOT>>>(E0f, Wimg + (OF_D0A + 4) * WCH4, A0, CN0, inv0, B1, cl0);
    k_agg128<false, true><<<(CN0 + 7) / 8, aggB>>>(A0, (float4*)B0, rp0, col0, inv0,
                                                   b_d0a, nullptr, nullptr, CN0);
    k_gemm_mma<false, true><<<GB0, 256, SMB_TOT>>>(B0, Wimg + OF_D0B * WCH4, A0, CN0, inv0, nullptr, nullptr);
    k_agg128_head<<<(CN0 + 7) / 8, aggB>>>((const __half2*)A0, out, rp0, col0, inv0, b_d0b,
                                           w_out, b_out, CN0);

    (void)in_sizes; (void)n_in; (void)out_size;
}

// round 16
// speedup vs baseline: 1.0525x; 1.0525x over previous
#include <cuda_runtime.h>
#include <cuda_bf16.h>
#include <cuda_fp16.h>
#include <cstdint>

#define CN0 200000
#define CN1 50000
#define CN2 12500
#define CE0 3200000
#define CE1 800000
#define CE2 200000
#define NT (CN0 + CN1 + CN2)
#define ET (CE0 + CE1 + CE2)

// ---------------- scratch ----------------
__device__ __align__(16) float g_A0[CN0 * 128];   // half-aliased agg input
__device__ __align__(16) float g_B0[CN0 * 128];
__device__ __align__(16) float g_E0[CN0 * 128];
__device__ __align__(16) float g_T0[CN0 * 4];
__device__ __align__(16) float g_XS[CN0 * 4];
__device__ __align__(16) float g_X1[CN1 * 128];
__device__ __align__(16) float g_A1[CN1 * 128];   // half-aliased agg input
__device__ __align__(16) float g_B1[CN1 * 128];
__device__ __align__(16) float g_E1[CN1 * 128];
__device__ __align__(16) float g_X2[CN2 * 128];
__device__ __align__(16) float g_A2[CN2 * 128];   // half-aliased agg input
__device__ __align__(16) float g_Y2[CN2 * 128];   // fp32 y_top2 (addsrc)
__device__ __align__(16) float g_BT[CN2 * 128];

__device__ int   g_degA[NT];
__device__ int   g_curA[NT];
__device__ float g_invA[NT];
__device__ int   g_rpA[NT + 3];
__device__ int   g_bsumA[66];
__device__ int   g_col0[CE0];
__device__ int   g_col1[CE1];
__device__ int   g_col2[CE2];

#define WCH4 1152
__device__ __align__(16) uint4 g_W[44 * WCH4];

#define SCAN_CHUNK 4096

struct EArgs {
    const int* s0; const int* d0;
    const int* s1; const int* d1;
    const int* s2; const int* d2;
};

// ---------------- merged CSR build ----------------
__global__ void k_deg_all(EArgs ea, int* __restrict__ degA) {
    int i = blockIdx.x * blockDim.x + threadIdx.x;
    if (i >= ET) return;
    int d, off;
    if (i < CE0)            { d = ea.d0[i]; off = 0; }
    else if (i < CE0 + CE1) { d = ea.d1[i - CE0]; off = CN0; }
    else                    { d = ea.d2[i - CE0 - CE1]; off = CN0 + CN1; }
    atomicAdd(&degA[off + d], 1);
}

__global__ void k_scan_part_all(const int* __restrict__ degA, int* __restrict__ bsum) {
    __shared__ int wsum[32];
    int b = blockIdx.x;
    int lb, n, doff;
    if (b < 49)      { lb = b;      n = CN0; doff = 0; }
    else if (b < 62) { lb = b - 49; n = CN1; doff = CN0; }
    else             { lb = b - 62; n = CN2; doff = CN0 + CN1; }
    const int* deg = degA + doff;
    int base = lb * SCAN_CHUNK + threadIdx.x * 4;
    int s = 0;
#pragma unroll
    for (int j = 0; j < 4; j++) if (base + j < n) s += deg[base + j];
    int lane = threadIdx.x & 31, wid = threadIdx.x >> 5;
#pragma unroll
    for (int off = 16; off > 0; off >>= 1) s += __shfl_down_sync(0xFFFFFFFFu, s, off);
    if (lane == 0) wsum[wid] = s;
    __syncthreads();
    if (threadIdx.x < 32) {
        int v = wsum[threadIdx.x];
#pragma unroll
        for (int off = 16; off > 0; off >>= 1) v += __shfl_down_sync(0xFFFFFFFFu, v, off);
        if (threadIdx.x == 0) bsum[b] = v;
    }
}

__global__ void k_scan_top_all(int* __restrict__ bsum, int* __restrict__ rpA) {
    int lv = blockIdx.x;
    int bstart = (lv == 0) ? 0 : (lv == 1) ? 49 : 62;
    int nb     = (lv == 0) ? 49 : (lv == 1) ? 13 : 4;
    int n      = (lv == 0) ? CN0 : (lv == 1) ? CN1 : CN2;
    int rpo    = (lv == 0) ? 0 : (lv == 1) ? CN0 + 1 : CN0 + CN1 + 2;
    int t = threadIdx.x;
    __shared__ int sh[64];
    sh[t] = (t < nb) ? bsum[bstart + t] : 0;
    __syncthreads();
    for (int off = 1; off < 64; off <<= 1) {
        int v = (t >= off) ? sh[t - off] : 0;
        __syncthreads();
        sh[t] += v;
        __syncthreads();
    }
    if (t < nb) bsum[bstart + t] = (t == 0) ? 0 : sh[t - 1];
    if (t == 63) rpA[rpo + n] = sh[63];
}

__global__ void k_scan_down_all(const int* __restrict__ degA, const int* __restrict__ bsum,
                                int* __restrict__ rpA, int* __restrict__ curA,
                                float* __restrict__ invA,
                                const float4* __restrict__ x, float4* __restrict__ xs) {
    __shared__ int wsum[32];
    int b = blockIdx.x;
    int lv, lb, n, doff, rpo;
    if (b < 49)      { lv = 0; lb = b;      n = CN0; doff = 0;        rpo = 0; }
    else if (b < 62) { lv = 1; lb = b - 49; n = CN1; doff = CN0;      rpo = CN0 + 1; }
    else             { lv = 2; lb = b - 62; n = CN2; doff = CN0 + CN1; rpo = CN0 + CN1 + 2; }
    const int* deg = degA + doff;
    int* rp = rpA + rpo;
    int* cur = curA + doff;
    float* inv = invA + doff;

    int base = lb * SCAN_CHUNK + threadIdx.x * 4;
    int d[4];
#pragma unroll
    for (int j = 0; j < 4; j++) d[j] = (base + j < n) ? deg[base + j] : 0;
    int tot = d[0] + d[1] + d[2] + d[3];
    int lane = threadIdx.x & 31, wid = threadIdx.x >> 5;
    int sc = tot;
#pragma unroll
    for (int off = 1; off < 32; off <<= 1) {
        int v = __shfl_up_sync(0xFFFFFFFFu, sc, off);
        if (lane >= off) sc += v;
    }
    if (lane == 31) wsum[wid] = sc;
    __syncthreads();
    if (threadIdx.x < 32) {
        int v = wsum[threadIdx.x];
#pragma unroll
        for (int off = 1; off < 32; off <<= 1) {
            int u = __shfl_up_sync(0xFFFFFFFFu, v, off);
            if (threadIdx.x >= off) v += u;
        }
        wsum[threadIdx.x] = v;
    }
    __syncthreads();
    int run = bsum[b] + (sc - tot) + (wid > 0 ? wsum[wid - 1] : 0);
#pragma unroll
    for (int j = 0; j < 4; j++) {
        int row = base + j;
        if (row < n) {
            rp[row] = run;
            cur[row] = run;
            float iv = rsqrtf((float)(d[j] + 1));
            inv[row] = iv;
            if (lv == 0) {
                float4 v = x[row];
                xs[row] = make_float4(v.x * iv, v.y * iv, v.z * iv, v.w * iv);
            }
            run += d[j];
        }
    }
}

__global__ void k_fill_all(EArgs ea, int* __restrict__ curA,
                           int* __restrict__ col0, int* __restrict__ col1,
                           int* __restrict__ col2) {
    int i = blockIdx.x * blockDim.x + threadIdx.x;
    if (i >= ET) return;
    int s, d, off;
    int* col;
    if (i < CE0)            { s = ea.s0[i]; d = ea.d0[i]; off = 0; col = col0; }
    else if (i < CE0 + CE1) { int e = i - CE0; s = ea.s1[e]; d = ea.d1[e]; off = CN0; col = col1; }
    else                    { int e = i - CE0 - CE1; s = ea.s2[e]; d = ea.d2[e]; off = CN0 + CN1; col = col2; }
    int p = atomicAdd(&curA[off + d], 1);
    col[p] = s;
}

// ---------------- aggregation over 4-wide pre-scaled features ----------------
__global__ void k_agg4(const float4* __restrict__ xs, float4* __restrict__ out,
                       const int* __restrict__ rp, const int* __restrict__ col,
                       const float* __restrict__ inv, int n) {
    int r = blockIdx.x * blockDim.x + threadIdx.x;
    if (r >= n) return;
    float4 acc = xs[r];
    int e = rp[r], end = rp[r + 1];
    for (; e + 4 <= end; e += 4) {
        int s0 = col[e], s1 = col[e + 1], s2 = col[e + 2], s3 = col[e + 3];
        float4 v0 = xs[s0], v1 = xs[s1], v2 = xs[s2], v3 = xs[s3];
        acc.x += v0.x + v1.x + v2.x + v3.x;
        acc.y += v0.y + v1.y + v2.y + v3.y;
        acc.z += v0.z + v1.z + v2.z + v3.z;
        acc.w += v0.w + v1.w + v2.w + v3.w;
    }
    for (; e < end; e++) {
        float4 v0 = xs[col[e]];
        acc.x += v0.x; acc.y += v0.y; acc.z += v0.z; acc.w += v0.w;
    }
    float invd = inv[r];
    out[r] = make_float4(acc.x * invd, acc.y * invd, acc.z * invd, acc.w * invd);
}

// ---------------- half-row load helper ----------------
__device__ __forceinline__ float4 ld_half4(const __half2* hp, int row, int lane) {
    uint2 u = *(const uint2*)(hp + (size_t)row * 64 + lane * 2);
    __half2 p0 = *(__half2*)&u.x;
    __half2 p1 = *(__half2*)&u.y;
    float2 f0 = __half22float2(p0);
    float2 f1 = __half22float2(p1);
    return make_float4(f0.x, f0.y, f1.x, f1.y);
}

// ---------------- aggregation 128-wide + bias + relu ----------------
template <bool POOL, bool HALF_IN>
__global__ void k_agg128(const void* __restrict__ hv, float4* __restrict__ out,
                         const int* __restrict__ rp, const int* __restrict__ col,
                         const float* __restrict__ inv, const float* __restrict__ bias,
                         int* __restrict__ pool, const int* __restrict__ clusters, int n) {
    int row = blockIdx.x * blockDim.y + threadIdx.y;
    if (row >= n) return;
    int lane = threadIdx.x;
    const float4* hf = (const float4*)hv;
    const __half2* hh = (const __half2*)hv;
    float4 acc = HALF_IN ? ld_half4(hh, row, lane) : hf[row * 32 + lane];
    int e = rp[row], end = rp[row + 1];
    for (; e + 4 <= end; e += 4) {
        int s0 = col[e], s1 = col[e + 1], s2 = col[e + 2], s3 = col[e + 3];
        float4 v0, v1, v2, v3;
        if (HALF_IN) {
            v0 = ld_half4(hh, s0, lane); v1 = ld_half4(hh, s1, lane);
            v2 = ld_half4(hh, s2, lane); v3 = ld_half4(hh, s3, lane);
        } else {
            v0 = hf[s0 * 32 + lane]; v1 = hf[s1 * 32 + lane];
            v2 = hf[s2 * 32 + lane]; v3 = hf[s3 * 32 + lane];
        }
        acc.x += v0.x + v1.x + v2.x + v3.x;
        acc.y += v0.y + v1.y + v2.y + v3.y;
        acc.z += v0.z + v1.z + v2.z + v3.z;
        acc.w += v0.w + v1.w + v2.w + v3.w;
    }
    for (; e < end; e++) {
        float4 v0 = HALF_IN ? ld_half4(hh, col[e], lane) : hf[col[e] * 32 + lane];
        acc.x += v0.x; acc.y += v0.y; acc.z += v0.z; acc.w += v0.w;
    }
    float invd = inv[row];
    int cb = lane * 4;
    acc.x = fmaxf(acc.x * invd + bias[cb + 0], 0.f);
    acc.y = fmaxf(acc.y * invd + bias[cb + 1], 0.f);
    acc.z = fmaxf(acc.z * invd + bias[cb + 2], 0.f);
    acc.w = fmaxf(acc.w * invd + bias[cb + 3], 0.f);
    out[row * 32 + lane] = acc;
    if (POOL) {
        int c = clusters[row];
        int base = c * 128 + cb;
        atomicMax(&pool[base + 0], __float_as_int(acc.x));
        atomicMax(&pool[base + 1], __float_as_int(acc.y));
        atomicMax(&pool[base + 2], __float_as_int(acc.z));
        atomicMax(&pool[base + 3], __float_as_int(acc.w));
    }
}

// ---------------- final aggregation fused with output head (half input) ----------------
__global__ void k_agg128_head(const __half2* __restrict__ hh, float* __restrict__ out,
                              const int* __restrict__ rp, const int* __restrict__ col,
                              const float* __restrict__ inv, const float* __restrict__ bias,
                              const float* __restrict__ wout, const float* __restrict__ bout,
                              int n) {
    int row = blockIdx.x * blockDim.y + threadIdx.y;
    if (row >= n) return;
    int lane = threadIdx.x;
    float4 acc = ld_half4(hh, row, lane);
    int e = rp[row], end = rp[row + 1];
    for (; e + 4 <= end; e += 4) {
        int s0 = col[e], s1 = col[e + 1], s2 = col[e + 2], s3 = col[e + 3];
        float4 v0 = ld_half4(hh, s0, lane);
        float4 v1 = ld_half4(hh, s1, lane);
        float4 v2 = ld_half4(hh, s2, lane);
        float4 v3 = ld_half4(hh, s3, lane);
        acc.x += v0.x + v1.x + v2.x + v3.x;
        acc.y += v0.y + v1.y + v2.y + v3.y;
        acc.z += v0.z + v1.z + v2.z + v3.z;
        acc.w += v0.w + v1.w + v2.w + v3.w;
    }
    for (; e < end; e++) {
        float4 v0 = ld_half4(hh, col[e], lane);
        acc.x += v0.x; acc.y += v0.y; acc.z += v0.z; acc.w += v0.w;
    }
    float invd = inv[row];
    int cb = lane * 4;
    float a0 = fmaxf(acc.x * invd + bias[cb + 0], 0.f);
    float a1 = fmaxf(acc.y * invd + bias[cb + 1], 0.f);
    float a2 = fmaxf(acc.z * invd + bias[cb + 2], 0.f);
    float a3 = fmaxf(acc.w * invd + bias[cb + 3], 0.f);
    float4 wv = *(const float4*)&wout[cb];
    float s = a0 * wv.x + a1 * wv.y + a2 * wv.z + a3 * wv.w;
#pragma unroll
    for (int off = 16; off > 0; off >>= 1) s += __shfl_down_sync(0xFFFFFFFFu, s, off);
    if (lane == 0) out[row] = s + bout[0];
}

// ---------------- bf16 split helpers ----------------
__device__ __forceinline__ void bf16_split2(float a, float b, uint32_t& hi, uint32_t& lo) {
    __nv_bfloat16 ah = __float2bfloat16(a);
    __nv_bfloat16 bh = __float2bfloat16(b);
    __nv_bfloat16 al = __float2bfloat16(a - __bfloat162float(ah));
    __nv_bfloat16 bl = __float2bfloat16(b - __bfloat162float(bh));
    hi = ((uint32_t)__bfloat16_as_ushort(bh) << 16) | (uint32_t)__bfloat16_as_ushort(ah);
    lo = ((uint32_t)__bfloat16_as_ushort(bl) << 16) | (uint32_t)__bfloat16_as_ushort(al);
}

// ---------------- merged weight pre-split ----------------
struct WArgs { const float* w[9]; };

__global__ void k_wsplit_all(WArgs a, uint4* __restrict__ img) {
    const int starts[10] = {0, 4, 8, 12, 16, 20, 24, 28, 36, 44};
    int b = blockIdx.x, tid = threadIdx.x;
    int wi = 0;
#pragma unroll
    for (int q = 0; q < 9; q++) if (b >= starts[q + 1]) wi = q + 1;
    int lc = b - starts[wi];
    const float* W = a.w[wi];
    uint4* out = img + b * WCH4;
#pragma unroll
    for (int it = 0; it < 4; it++) {
        int p = tid + it * 256;
        int cn = p >> 3, r = p & 7, ks = r >> 2, t = r & 3;
        int k0 = lc * 32 + ks * 16 + 2 * t;
        float w00 = W[(size_t)k0 * 128 + cn];
        float w01 = W[(size_t)(k0 + 1) * 128 + cn];
        float w10 = W[(size_t)(k0 + 8) * 128 + cn];
        float w11 = W[(size_t)(k0 + 9) * 128 + cn];
        uint32_t h0, l0, h1, l1;
        bf16_split2(w00, w01, h0, l0);
        bf16_split2(w10, w11, h1, l1);
        out[cn * 9 + ks * 4 + t] = make_uint4(h0, h1, l0, l1);
    }
    for (int p = tid; p < 128; p += 256) out[p * 9 + 8] = make_uint4(0, 0, 0, 0);
}

// =====================================================================
//  bf16 mma.sync GEMM
// =====================================================================
#define SMB_A 16384
#define SMB_W (WCH4 * 16)
#define SMB_RAW 16384
#define SMB_RAW_OFF (SMB_A + 2 * SMB_W)
#define SMB_TOT (SMB_RAW_OFF + 2 * SMB_RAW)
#define SMB_TOT_E0 (SMB_RAW_OFF + 2560)

__device__ __forceinline__ uint32_t smem_u32(const void* p) {
    uint32_t a;
    asm("{ .reg .u64 t; cvta.to.shared.u64 t, %1; cvt.u32.u64 %0, t; }" : "=r"(a) : "l"(p));
    return a;
}

__device__ __forceinline__ void cpa16(uint32_t saddr, const void* g) {
    asm volatile("cp.async.cg.shared.global [%0], [%1], 16;" :: "r"(saddr), "l"(g) : "memory");
}

__device__ __forceinline__ void cpa16z(uint32_t saddr, const void* g, int sz) {
    asm volatile("cp.async.cg.shared.global [%0], [%1], 16, %2;"
                 :: "r"(saddr), "l"(g), "r"(sz) : "memory");
}

__device__ __forceinline__ void copy_w_chunk(uint32_t sdst, const uint4* gsrc, int tid) {
#pragma unroll
    for (int it = 0; it < 5; it++) {
        int g = tid + it * 256;
        if (g < WCH4) cpa16(sdst + g * 16, gsrc + g);
    }
}

__device__ __forceinline__ void copy_a_chunk(uint32_t sdst, const float* A, int r0,
                                             int kc, int n, int tid) {
#pragma unroll
    for (int it = 0; it < 4; it++) {
        int g = tid + it * 256;
        int row = g >> 3, seg = g & 7;
        const float* src = A + (size_t)(r0 + row) * 128 + kc + seg * 4;
        int sz = (r0 + row < n) ? 16 : 0;
        cpa16z(sdst + g * 16, src, sz);
    }
}

__device__ __forceinline__ void mma_bf16(float* c, uint4 a, uint32_t b0, uint32_t b1) {
    asm volatile(
        "mma.sync.aligned.m16n8k16.row.col.f32.bf16.bf16.f32 "
        "{%0,%1,%2,%3}, {%4,%5,%6,%7}, {%8,%9}, {%0,%1,%2,%3};"
        : "+f"(c[0]), "+f"(c[1]), "+f"(c[2]), "+f"(c[3])
        : "r"(a.x), "r"(a.y), "r"(a.z), "r"(a.w), "r"(b0), "r"(b1));
}

template <bool HALF_OUT>
__device__ __forceinline__ void st_out(float* Cm, int row, int cn, float2 o) {
    if (HALF_OUT) {
        __half2 h = __floats2half2_rn(o.x, o.y);
        ((__half2*)Cm)[(size_t)row * 64 + (cn >> 1)] = h;
    } else {
        *(float2*)&Cm[(size_t)row * 128 + cn] = o;
    }
}

template <bool ADD_GATHER, bool HALF_OUT>
__global__ void __launch_bounds__(256, 2) k_gemm_mma(
    const float* __restrict__ A, const uint4* __restrict__ gW,
    float* __restrict__ Cm, int n,
    const float* __restrict__ scale,
    const float* __restrict__ addsrc, const int* __restrict__ gidx) {
    extern __shared__ char smem[];
    uint32_t* AHu = (uint32_t*)smem;
    uint32_t* ALu = AHu + 2048;
    const uint4* AH4 = (const uint4*)smem;
    const uint4* AL4 = AH4 + 512;
    uint32_t sb = smem_u32(smem);

    int tid = threadIdx.x;
    int warp = tid >> 5, lane = tid & 31;
    int g = lane >> 2, t = lane & 3;
    int mrow = (warp & 3) * 32;
    int ncol = (warp >> 2) * 64;
    int r0 = blockIdx.x * 128;

    float c[2][8][4];
#pragma unroll
    for (int i = 0; i < 2; i++)
#pragma unroll
        for (int j = 0; j < 8; j++)
#pragma unroll
            for (int q = 0; q < 4; q++) c[i][j][q] = 0.f;

    copy_w_chunk(sb + SMB_A, gW, tid);
    copy_a_chunk(sb + SMB_RAW_OFF, A, r0, 0, n, tid);
    asm volatile("cp.async.commit_group;" ::: "memory");

#pragma unroll
    for (int cc = 0; cc < 4; cc++) {
        if (cc < 3) {
            int nb = (cc + 1) & 1;
            copy_w_chunk(sb + SMB_A + nb * SMB_W, gW + (cc + 1) * WCH4, tid);
            copy_a_chunk(sb + SMB_RAW_OFF + nb * SMB_RAW, A, r0, (cc + 1) * 32, n, tid);
            asm volatile("cp.async.commit_group;" ::: "memory");
            asm volatile("cp.async.wait_group 1;" ::: "memory");
        } else {
            asm volatile("cp.async.wait_group 0;" ::: "memory");
        }
        __syncthreads();

        const float* raw = (const float*)(smem + SMB_RAW_OFF + (cc & 1) * SMB_RAW);
#pragma unroll
        for (int it = 0; it < 8; it++) {
            int p = tid + it * 256;
            int row = p >> 4, kp = p & 15;
            float2 av = *(const float2*)&raw[row * 32 + 2 * kp];
            uint32_t hi, lo;
            bf16_split2(av.x, av.y, hi, lo);
            int s = row & 15, rg = row >> 4;
            int ks = kp >> 3, kp8 = kp & 7, tt = kp8 & 3, half = kp8 >> 2;
            int idx = (((rg * 2 + ks) * 32) + (s & 7) * 4 + tt) * 4 + half * 2 + (s >> 3);
            AHu[idx] = hi;
            ALu[idx] = lo;
        }
        __syncthreads();

        const uint4* B4 = (const uint4*)(smem + SMB_A + (cc & 1) * SMB_W);

#pragma unroll
        for (int ks = 0; ks < 2; ks++) {
            uint4 ah[2], al[2];
#pragma unroll
            for (int i = 0; i < 2; i++) {
                int grp = (((warp & 3) * 2 + i) * 2 + ks) * 32 + lane;
                ah[i] = AH4[grp];
                al[i] = AL4[grp];
            }
#pragma unroll
            for (int j = 0; j < 8; j++) {
                int cn = ncol + j * 8 + g;
                uint4 b4 = B4[cn * 9 + ks * 4 + t];
#pragma unroll
                for (int i = 0; i < 2; i++) {
                    mma_bf16(c[i][j], ah[i], b4.x, b4.y);
                    mma_bf16(c[i][j], al[i], b4.x, b4.y);
                    mma_bf16(c[i][j], ah[i], b4.z, b4.w);
                }
            }
        }
        __syncthreads();
    }

#pragma unroll
    for (int i = 0; i < 2; i++) {
        int rowA = r0 + mrow + i * 16 + g;
        int rowB = rowA + 8;
        int gA = 0, gB = 0;
        float sA = 1.f, sB = 1.f;
        if (ADD_GATHER) {
            if (rowA < n) gA = gidx[rowA];
            if (rowB < n) gB = gidx[rowB];
        }
        if (scale) {
            if (rowA < n) sA = scale[rowA];
            if (rowB < n) sB = scale[rowB];
        }
#pragma unroll
        for (int j = 0; j < 8; j++) {
            int cn = ncol + j * 8 + 2 * t;
            if (rowA < n) {
                float2 o = make_float2(c[i][j][0], c[i][j][1]);
                if (ADD_GATHER) {
                    o.x += addsrc[(size_t)gA * 128 + cn];
                    o.y += addsrc[(size_t)gA * 128 + cn + 1];
                }
                o.x *= sA; o.y *= sA;
                st_out<HALF_OUT>(Cm, rowA, cn, o);
            }
            if (rowB < n) {
                float2 o = make_float2(c[i][j][2], c[i][j][3]);
                if (ADD_GATHER) {
                    o.x += addsrc[(size_t)gB * 128 + cn];
                    o.y += addsrc[(size_t)gB * 128 + cn + 1];
                }
                o.x *= sB; o.y *= sB;
                st_out<HALF_OUT>(Cm, rowB, cn, o);
            }
        }
    }
}

// fused first-layer variant (half output)
__global__ void __launch_bounds__(256, 2) k_gemm_e0(
    const float4* __restrict__ T0, const float* __restrict__ W0,
    const float* __restrict__ b0, const uint4* __restrict__ gW,
    float* __restrict__ Cm, int n, const float* __restrict__ scale) {
    extern __shared__ char smem[];
    uint32_t* AHu = (uint32_t*)smem;
    uint32_t* ALu = AHu + 2048;
    const uint4* AH4 = (const uint4*)smem;
    const uint4* AL4 = AH4 + 512;
    float* Ws = (float*)(smem + SMB_RAW_OFF);
    float* Bs = Ws + 512;
    uint32_t sb = smem_u32(smem);

    int tid = threadIdx.x;
    int warp = tid >> 5, lane = tid & 31;
    int g = lane >> 2, t = lane & 3;
    int mrow = (warp & 3) * 32;
    int ncol = (warp >> 2) * 64;
    int r0 = blockIdx.x * 128;

    for (int i = tid; i < 512; i += 256) Ws[i] = W0[i];
    if (tid < 128) Bs[tid] = b0[tid];

    float c[2][8][4];
#pragma unroll
    for (int i = 0; i < 2; i++)
#pragma unroll
        for (int j = 0; j < 8; j++)
#pragma unroll
            for (int q = 0; q < 4; q++) c[i][j][q] = 0.f;

    copy_w_chunk(sb + SMB_A, gW, tid);
    asm volatile("cp.async.commit_group;" ::: "memory");
    __syncthreads();

#pragma unroll
    for (int cc = 0; cc < 4; cc++) {
        int kc = cc * 32;
#pragma unroll
        for (int it = 0; it < 8; it++) {
            int p = tid + it * 256;
            int row = p >> 4, kp = p & 15;
            float v0 = 0.f, v1 = 0.f;
            if (r0 + row < n) {
                float4 t4 = T0[r0 + row];
                int cx = kc + 2 * kp;
                v0 = fmaxf(Bs[cx] + t4.x * Ws[cx] + t4.y * Ws[128 + cx]
                           + t4.z * Ws[256 + cx] + t4.w * Ws[384 + cx], 0.f);
                v1 = fmaxf(Bs[cx + 1] + t4.x * Ws[cx + 1] + t4.y * Ws[128 + cx + 1]
                           + t4.z * Ws[256 + cx + 1] + t4.w * Ws[384 + cx + 1], 0.f);
            }
            uint32_t hi, lo;
            bf16_split2(v0, v1, hi, lo);
            int s = row & 15, rg = row >> 4;
            int ks = kp >> 3, kp8 = kp & 7, tt = kp8 & 3, half = kp8 >> 2;
            int idx = (((rg * 2 + ks) * 32) + (s & 7) * 4 + tt) * 4 + half * 2 + (s >> 3);
            AHu[idx] = hi;
            ALu[idx] = lo;
        }
        if (cc < 3) {
            copy_w_chunk(sb + SMB_A + ((cc + 1) & 1) * SMB_W, gW + (cc + 1) * WCH4, tid);
            asm volatile("cp.async.commit_group;" ::: "memory");
            asm volatile("cp.async.wait_group 1;" ::: "memory");
        } else {
            asm volatile("cp.async.wait_group 0;" ::: "memory");
        }
        __syncthreads();

        const uint4* B4 = (const uint4*)(smem + SMB_A + (cc & 1) * SMB_W);

#pragma unroll
        for (int ks = 0; ks < 2; ks++) {
            uint4 ah[2], al[2];
#pragma unroll
            for (int i = 0; i < 2; i++) {
                int grp = (((warp & 3) * 2 + i) * 2 + ks) * 32 + lane;
                ah[i] = AH4[grp];
                al[i] = AL4[grp];
            }
#pragma unroll
            for (int j = 0; j < 8; j++) {
                int cn = ncol + j * 8 + g;
                uint4 b4 = B4[cn * 9 + ks * 4 + t];
#pragma unroll
                for (int i = 0; i < 2; i++) {
                    mma_bf16(c[i][j], ah[i], b4.x, b4.y);
                    mma_bf16(c[i][j], al[i], b4.x, b4.y);
                    mma_bf16(c[i][j], ah[i], b4.z, b4.w);
                }
            }
        }
        __syncthreads();
    }

#pragma unroll
    for (int i = 0; i < 2; i++) {
        int rowA = r0 + mrow + i * 16 + g;
        int rowB = rowA + 8;
        float sA = (rowA < n) ? scale[rowA] : 1.f;
        float sB = (rowB < n) ? scale[rowB] : 1.f;
#pragma unroll
        for (int j = 0; j < 8; j++) {
            int cn = ncol + j * 8 + 2 * t;
            if (rowA < n)
                st_out<true>(Cm, rowA, cn, make_float2(c[i][j][0] * sA, c[i][j][1] * sA));
            if (rowB < n)
                st_out<true>(Cm, rowB, cn, make_float2(c[i][j][2] * sB, c[i][j][3] * sB));
        }
    }
}

// ---------------- host ----------------
static inline void* symaddr(const void* sym) {
    void* p = nullptr;
    cudaGetSymbolAddress(&p, sym);
    return p;
}

extern "C" void kernel_launch(void* const* d_in, const int* in_sizes, int n_in,
                              void* d_out, int out_size) {
    const float* x     = (const float*)d_in[0];
    const int*   ei0   = (const int*)d_in[1];
    const int*   ei1   = (const int*)d_in[2];
    const int*   ei2   = (const int*)d_in[3];
    const int*   cl0   = (const int*)d_in[4];
    const int*   cl1   = (const int*)d_in[5];
    const float* w_e0a = (const float*)d_in[6];  const float* b_e0a = (const float*)d_in[7];
    const float* w_e0b = (const float*)d_in[8];  const float* b_e0b = (const float*)d_in[9];
    const float* w_e1a = (const float*)d_in[10]; const float* b_e1a = (const float*)d_in[11];
    const float* w_e1b = (const float*)d_in[12]; const float* b_e1b = (const float*)d_in[13];
    const float* w_ba  = (const float*)d_in[14]; const float* b_ba  = (const float*)d_in[15];
    const float* w_bb  = (const float*)d_in[16]; const float* b_bb  = (const float*)d_in[17];
    const float* w_d1a = (const float*)d_in[18]; const float* b_d1a = (const float*)d_in[19];
    const float* w_d1b = (const float*)d_in[20]; const float* b_d1b = (const float*)d_in[21];
    const float* w_d0a = (const float*)d_in[22]; const float* b_d0a = (const float*)d_in[23];
    const float* w_d0b = (const float*)d_in[24]; const float* b_d0b = (const float*)d_in[25];
    const float* w_out = (const float*)d_in[26]; const float* b_out = (const float*)d_in[27];
    float* out = (float*)d_out;

    float* A0 = (float*)symaddr(g_A0);
    float* B0 = (float*)symaddr(g_B0);
    float* E0f = (float*)symaddr(g_E0); float* T0 = (float*)symaddr(g_T0);
    float* XS = (float*)symaddr(g_XS);
    float* X1 = (float*)symaddr(g_X1); float* A1 = (float*)symaddr(g_A1);
    float* B1 = (float*)symaddr(g_B1); float* E1f = (float*)symaddr(g_E1);
    float* X2 = (float*)symaddr(g_X2); float* A2 = (float*)symaddr(g_A2);
    float* Y2 = (float*)symaddr(g_Y2);
    float* BT = (float*)symaddr(g_BT);

    int* degA = (int*)symaddr(g_degA);
    int* curA = (int*)symaddr(g_curA);
    float* invA = (float*)symaddr(g_invA);
    int* rpA = (int*)symaddr(g_rpA);
    int* bsA = (int*)symaddr(g_bsumA);
    int* col0 = (int*)symaddr(g_col0);
    int* col1 = (int*)symaddr(g_col1);
    int* col2 = (int*)symaddr(g_col2);
    uint4* Wimg = (uint4*)symaddr(g_W);

    int* rp0 = rpA;
    int* rp1 = rpA + CN0 + 1;
    int* rp2 = rpA + CN0 + CN1 + 2;
    float* inv0 = invA;
    float* inv1 = invA + CN0;
    float* inv2 = invA + CN0 + CN1;

    cudaFuncSetAttribute(k_gemm_mma<false, false>, cudaFuncAttributeMaxDynamicSharedMemorySize, SMB_TOT);
    cudaFuncSetAttribute(k_gemm_mma<true, true>,   cudaFuncAttributeMaxDynamicSharedMemorySize, SMB_TOT);
    cudaFuncSetAttribute(k_gemm_mma<false, true>,  cudaFuncAttributeMaxDynamicSharedMemorySize, SMB_TOT);
    cudaFuncSetAttribute(k_gemm_e0, cudaFuncAttributeMaxDynamicSharedMemorySize, SMB_TOT_E0);

    const int T = 256;
    dim3 aggB(32, 8);
    const int GB0 = (CN0 + 127) / 128, GB1 = (CN1 + 127) / 128, GB2 = (CN2 + 127) / 128;

    const int OF_E0B = 0, OF_E1A = 4, OF_E1B = 8, OF_BA = 12, OF_BB = 16,
              OF_D1B = 20, OF_D0B = 24, OF_D1A = 28, OF_D0A = 36;

    // ---- merged weight pre-split ----
    WArgs wa;
    wa.w[0] = w_e0b; wa.w[1] = w_e1a; wa.w[2] = w_e1b; wa.w[3] = w_ba; wa.w[4] = w_bb;
    wa.w[5] = w_d1b; wa.w[6] = w_d0b; wa.w[7] = w_d1a; wa.w[8] = w_d0a;
    k_wsplit_all<<<44, 256>>>(wa, Wimg);

    // ---- merged CSR build ----
    EArgs ea;
    ea.s0 = ei0; ea.d0 = ei0 + CE0;
    ea.s1 = ei1; ea.d1 = ei1 + CE1;
    ea.s2 = ei2; ea.d2 = ei2 + CE2;
    cudaMemsetAsync(degA, 0, NT * sizeof(int));
    cudaMemsetAsync(X1, 0, (size_t)CN1 * 128 * sizeof(float));
    cudaMemsetAsync(X2, 0, (size_t)CN2 * 128 * sizeof(float));
    k_deg_all<<<(ET + T - 1) / T, T>>>(ea, degA);
    k_scan_part_all<<<66, 1024>>>(degA, bsA);
    k_scan_top_all<<<3, 64>>>(bsA, rpA);
    k_scan_down_all<<<66, 1024>>>(degA, bsA, rpA, curA, invA, (const float4*)x, (float4*)XS);
    k_fill_all<<<(ET + T - 1) / T, T>>>(ea, curA, col0, col1, col2);

    // ---- encoder level 0 (A0 fp16) ----
    k_agg4<<<(CN0 + T - 1) / T, T>>>((const float4*)XS, (float4*)T0, rp0, col0, inv0, CN0);
    k_gemm_e0<<<GB0, 256, SMB_TOT_E0>>>((const float4*)T0, w_e0a, b_e0a,
                                        Wimg + OF_E0B * WCH4, A0, CN0, inv0);
    k_agg128<true, true><<<(CN0 + 7) / 8, aggB>>>(A0, (float4*)E0f, rp0, col0, inv0,
                                                  b_e0b, (int*)X1, cl0, CN0);

    // ---- encoder level 1 (A1 fp16) ----
    k_gemm_mma<false, true><<<GB1, 256, SMB_TOT>>>(X1, Wimg + OF_E1A * WCH4, A1, CN1, inv1, nullptr, nullptr);
    k_agg128<false, true><<<(CN1 + 7) / 8, aggB>>>(A1, (float4*)B1, rp1, col1, inv1,
                                                   b_e1a, nullptr, nullptr, CN1);
    k_gemm_mma<false, true><<<GB1, 256, SMB_TOT>>>(B1, Wimg + OF_E1B * WCH4, A1, CN1, inv1, nullptr, nullptr);
    k_agg128<true, true><<<(CN1 + 7) / 8, aggB>>>(A1, (float4*)E1f, rp1, col1, inv1,
                                                  b_e1b, (int*)X2, cl1, CN1);

    // ---- bottom level 2 (A2 fp16) ----
    k_gemm_mma<false, true><<<GB2, 256, SMB_TOT>>>(X2, Wimg + OF_BA * WCH4, A2, CN2, inv2, nullptr, nullptr);
    k_agg128<false, true><<<(CN2 + 7) / 8, aggB>>>(A2, (float4*)BT, rp2, col2, inv2,
                                                   b_ba, nullptr, nullptr, CN2);
    k_gemm_mma<false, true><<<GB2, 256, SMB_TOT>>>(BT, Wimg + OF_BB * WCH4, A2, CN2, inv2, nullptr, nullptr);
    k_agg128<false, true><<<(CN2 + 7) / 8, aggB>>>(A2, (float4*)BT, rp2, col2, inv2,
                                                   b_bb, nullptr, nullptr, CN2);

    // ---- decoder level 1 ----
    k_gemm_mma<false, false><<<GB2, 256, SMB_TOT>>>(BT, Wimg + OF_D1A * WCH4, Y2, CN2, nullptr, nullptr, nullptr);
    k_gemm_mma<true, true><<<GB1, 256, SMB_TOT>>>(E1f, Wimg + (OF_D1A + 4) * WCH4, A1, CN1, inv1, Y2, cl1);
    k_agg128<false, true><<<(CN1 + 7) / 8, aggB>>>(A1, (float4*)B1, rp1, col1, inv1,
                                                   b_d1a, nullptr, nullptr, CN1);
    k_gemm_mma<false, true><<<GB1, 256, SMB_TOT>>>(B1, Wimg + OF_D1B * WCH4, A1, CN1, inv1, nullptr, nullptr);
    k_agg128<false, true><<<(CN1 + 7) / 8, aggB>>>(A1, (float4*)X1, rp1, col1, inv1,
                                                   b_d1b, nullptr, nullptr, CN1);

    // ---- decoder level 0 ----
    k_gemm_mma<false, false><<<GB1, 256, SMB_TOT>>>(X1, Wimg + OF_D0A * WCH4, B1, CN1, nullptr, nullptr, nullptr);
    k_gemm_mma<true, true><<<GB0, 256, SMB_TOT>>>(E0f, Wimg + (OF_D0A + 4) * WCH4, A0, CN0, inv0, B1, cl0);
    k_agg128<false, true><<<(CN0 + 7) / 8, aggB>>>(A0, (float4*)B0, rp0, col0, inv0,
                                                   b_d0a, nullptr, nullptr, CN0);
    k_gemm_mma<false, true><<<GB0, 256, SMB_TOT>>>(B0, Wimg + OF_D0B * WCH4, A0, CN0, inv0, nullptr, nullptr);
    k_agg128_head<<<(CN0 + 7) / 8, aggB>>>((const __half2*)A0, out, rp0, col0, inv0, b_d0b,
                                           w_out, b_out, CN0);

    (void)in_sizes; (void)n_in; (void)out_size;
}